// round 15
// baseline (speedup 1.0000x reference)
#include <cuda_runtime.h>
#include <math.h>
#include <math_constants.h>

#define BATCH 64
#define DIM   768
#define HW    3136          // 56*56
#define FREQ  256
#define NE    16
#define TOPK  4

// scratch (device globals: zero-initialized; finish kernel restores zeros)
__device__ float g_logits_main[BATCH * NE];   // atomic-accumulated pooled @ gate_w.T
__device__ float g_logits_freq[BATCH * NE];   // freq_emb @ freq_gate_w.T (plain writes)

// ---------------------------------------------------------------------------
// Kernel A (primary): streaming pool + gating GEMM. One warp per (b,d) row,
// 8-deep ldcs float4 batches (87% DRAM). freq GEMM rides on the FIRST 1024
// warps (blocks 0..127 — wave 1 of 5.19), keeping the last partial wave —
// the blocks the PDL dependent waits on — uniformly minimal. NO block
// barriers anywhere (they stall cross-block warp pipelining: R3-R8 lesson).
// ---------------------------------------------------------------------------
__global__ void __launch_bounds__(256) pool_gate_kernel(
    const float* __restrict__ x,
    const float* __restrict__ gate_w,
    const float* __restrict__ freq_emb,
    const float* __restrict__ fgate_w) {

    // fire ASAP: dependent may launch once the last wave has STARTED
    asm volatile("griddepcontrol.launch_dependents;" ::: "memory");

    const int warp_id = (blockIdx.x * blockDim.x + threadIdx.x) >> 5;
    const int lane = threadIdx.x & 31;
    const int b = warp_id / DIM;
    const int d = warp_id - b * DIM;

    const float4* row = reinterpret_cast<const float4*>(x + (size_t)warp_id * HW);
    float s = 0.0f;
#pragma unroll
    for (int t = 0; t < 3; ++t) {           // 784 float4: 3 x (8 x 32 lanes) + 16
        float4 v[8];
#pragma unroll
        for (int k = 0; k < 8; ++k)
            v[k] = __ldcs(&row[lane + 32 * (t * 8 + k)]);
#pragma unroll
        for (int k = 0; k < 8; ++k)
            s += (v[k].x + v[k].y) + (v[k].z + v[k].w);
    }
    if (lane < 16) {
        float4 v = __ldcs(&row[768 + lane]);
        s += (v.x + v.y) + (v.z + v.w);
    }
#pragma unroll
    for (int m = 16; m; m >>= 1) s += __shfl_xor_sync(0xffffffffu, s, m);

    const float pooled = s * (1.0f / (float)HW);
    if (lane < NE)
        atomicAdd(&g_logits_main[b * NE + lane], pooled * gate_w[lane * DIM + d]);

    // freq-emb logits on the FIRST-WAVE warps only: (fb, fe) = (w>>4, w&15)
    if (warp_id < BATCH * NE) {
        const int fb = warp_id >> 4;
        const int fe = warp_id & 15;
        const float4* fr  = reinterpret_cast<const float4*>(freq_emb + fb * FREQ);
        const float4* fgr = reinterpret_cast<const float4*>(fgate_w  + fe * FREQ);
        float f = 0.0f;
#pragma unroll
        for (int j = 0; j < 2; ++j) {        // 64 float4 / 32 lanes
            float4 a = fr[lane + 32 * j];
            float4 w = fgr[lane + 32 * j];
            f += a.x * w.x + a.y * w.y + a.z * w.z + a.w * w.w;
        }
#pragma unroll
        for (int m = 16; m; m >>= 1) f += __shfl_xor_sync(0xffffffffu, f, m);
        if (lane == 0) g_logits_freq[warp_id] = f;
    }
}

// ---------------------------------------------------------------------------
// Kernel B (PDL secondary): ramps + preludes while the pool drains, parks in
// cudaGridDependencySynchronize (HW wait), then runs the epilogue.
// Aux reduction: transposed smem layout ([e*64+b], conflict-free columns) +
// warp-per-column sums -> only 2 barriers post-wait (was 6).
// Output (float32): gates[64*16] | top_k_indices[64*4] | top_k_values[64*4] | aux_loss
// ---------------------------------------------------------------------------
__global__ void finish_kernel(const float* __restrict__ noise,
                              const float* __restrict__ complexity,
                              float* __restrict__ out) {
    __shared__ float s_clean[BATCH * NE];   // transposed: [e*64 + b]
    __shared__ float s_p[BATCH * NE];       // transposed: [e*64 + b]
    __shared__ float s_red[2 * NE];         // [0:16) clean col sums, [16:32) p col sums

    const int tid  = threadIdx.x;          // 0..1023
    const int b    = tid >> 4;
    const int e    = tid & 15;
    const int lane = tid & 31;
    const int wid  = tid >> 5;             // 0..31
    const int half = lane & 16;            // base lane of my 16-lane group

    // ---- prelude: independent of the primary (overlaps pool drain) ----
    const float noise_std = 1.0f / (float)NE;
    const float my_noise  = noise[tid] * noise_std;
    const float my_cplx   = (tid < NE) ? complexity[tid] : 0.0f;

    // ---- HW wait for pool grid completion + memory visibility ----
    cudaGridDependencySynchronize();

    const float logit = g_logits_main[tid] + g_logits_freq[tid];
    g_logits_main[tid] = 0.0f;             // restore for next replay (own element)
    const float noisy = logit + my_noise;

    // softmaxes without max-subtraction (logits O(10); ratio identical)
    float ce  = __expf(logit);
    float ne_ = __expf(noisy);
    float cs = ce, ns = ne_;
#pragma unroll
    for (int m = 8; m; m >>= 1) {
        cs += __shfl_xor_sync(0xffffffffu, cs, m);
        ns += __shfl_xor_sync(0xffffffffu, ns, m);
    }
    const float clean = ce / cs;
    const float score = ne_ / ns;

    // rank of my noisy logit within the row (ties: lower index wins, jax top_k)
    int rank = 0;
#pragma unroll
    for (int j = 0; j < 16; ++j) {
        float vj = __shfl_sync(0xffffffffu, noisy, half + j);
        rank += (vj > noisy) || (vj == noisy && j < e);
    }

    // threshold = k-th largest noisy logit (rank == TOPK-1)
    float thr = (rank == TOPK - 1) ? noisy : -CUDART_INF_F;
#pragma unroll
    for (int m = 8; m; m >>= 1) thr = fmaxf(thr, __shfl_xor_sync(0xffffffffu, thr, m));

    // outputs: gates / indices / values
    out[tid] = (rank < TOPK) ? score : 0.0f;
    if (rank < TOPK) {
        out[BATCH * NE + b * TOPK + rank]                 = (float)e;  // indices
        out[BATCH * NE + BATCH * TOPK + b * TOPK + rank]  = score;     // values
    }

    // p = 1 - norm_cdf((thr - logit)/noise_std); store TRANSPOSED
    s_clean[e * BATCH + b] = clean;
    s_p[e * BATCH + b]     = 0.5f * erfcf((thr - logit) * (float)NE * 0.70710678118654752f);
    __syncthreads();                        // barrier 1

    // warp-per-column sums: warps 0..15 -> clean cols, 16..31 -> p cols
    {
        const float* src = (wid < NE) ? s_clean : s_p;
        const int col = wid & 15;
        float v = src[col * BATCH + lane] + src[col * BATCH + lane + 32];
#pragma unroll
        for (int m = 16; m; m >>= 1) v += __shfl_xor_sync(0xffffffffu, v, m);
        if (lane == 0) s_red[wid] = v;
    }
    __syncthreads();                        // barrier 2

    if (tid < 32) {
        float imp = 0.0f, pm = 0.0f;
        if (tid < 16) {
            imp = s_red[tid] * my_cplx;
            pm  = s_red[NE + tid] * (1.0f / (float)BATCH);
        }
        float im = imp, pmn = pm;
#pragma unroll
        for (int m = 8; m; m >>= 1) {
            im  += __shfl_xor_sync(0xffffffffu, im,  m);
            pmn += __shfl_xor_sync(0xffffffffu, pmn, m);
        }
        im  *= (1.0f / (float)NE);
        pmn *= (1.0f / (float)NE);
        float dv = (tid < 16) ? (imp - im)  * (imp - im)  : 0.0f;
        float dp = (tid < 16) ? (pm  - pmn) * (pm  - pmn) : 0.0f;
#pragma unroll
        for (int m = 8; m; m >>= 1) {
            dv += __shfl_xor_sync(0xffffffffu, dv, m);
            dp += __shfl_xor_sync(0xffffffffu, dp, m);
        }
        if (tid == 0) {
            float imp_loss  = (dv / (float)(NE - 1)) / ((im  + 1e-8f) * (im  + 1e-8f));
            float load_loss = (dp / (float)(NE - 1)) / ((pmn + 1e-8f) * (pmn + 1e-8f));
            out[BATCH * NE + 2 * BATCH * TOPK] = 0.5f * imp_loss + 0.5f * load_loss;
        }
    }
}

// ---------------------------------------------------------------------------
extern "C" void kernel_launch(void* const* d_in, const int* in_sizes, int n_in,
                              void* d_out, int out_size) {
    const float* x          = (const float*)d_in[0];
    const float* freq_emb   = (const float*)d_in[1];
    const float* gate_w     = (const float*)d_in[2];
    const float* fgate_w    = (const float*)d_in[3];
    const float* complexity = (const float*)d_in[4];
    const float* noise      = (const float*)d_in[5];
    float* out = (float*)d_out;

    // A: streaming pool + gating GEMM — 6144 blocks, 8 warps each
    pool_gate_kernel<<<(BATCH * DIM) / 8, 256>>>(x, gate_w, freq_emb, fgate_w);

    // B: epilogue with programmatic dependent launch (early-fired)
    cudaLaunchAttribute attrs[1];
    attrs[0].id = cudaLaunchAttributeProgrammaticStreamSerialization;
    attrs[0].val.programmaticStreamSerializationAllowed = 1;

    cudaLaunchConfig_t cfg = {};
    cfg.gridDim  = dim3(1, 1, 1);
    cfg.blockDim = dim3(BATCH * NE, 1, 1);
    cfg.dynamicSmemBytes = 0;
    cfg.stream = 0;
    cfg.attrs = attrs;
    cfg.numAttrs = 1;

    cudaLaunchKernelEx(&cfg, finish_kernel, noise, complexity, out);
}